// round 14
// baseline (speedup 1.0000x reference)
#include <cuda_runtime.h>
#include <cstdint>

#define SEQ_LEN    2048
#define STATE_LEN  1024
#define N_POI      10000
#define ROW_BYTES  (N_POI * 4)           // 40000, 16B-aligned
#define HEAD_ELEMS 4000
#define HEAD_BYTES (HEAD_ELEMS * 4)      // 16000, 16B-aligned
#define TAIL_BYTES (ROW_BYTES - HEAD_BYTES) // 24000
#define EPS_VAL    1e-6f
#define THREADS    256
#define PER_T      (SEQ_LEN / THREADS)   // 8
#define GRID       (STATE_LEN / 2)       // 512 CTAs -> single wave, 2 rows each

__device__ __forceinline__ void mbar_wait(uint32_t addr, uint32_t parity)
{
    uint32_t done;
    asm volatile(
        "{\n\t"
        ".reg .pred p;\n\t"
        "mbarrier.try_wait.parity.acquire.cta.shared::cta.b64 p, [%1], %2;\n\t"
        "selp.b32 %0, 1, 0, p;\n\t"
        "}"
        : "=r"(done) : "r"(addr), "r"(parity) : "memory");
    if (!done) {
        asm volatile(
            "{\n\t"
            ".reg .pred P1;\n\t"
            "W_%=:\n\t"
            "mbarrier.try_wait.parity.acquire.cta.shared::cta.b64 P1, [%0], %1, 0x989680;\n\t"
            "@P1 bra.uni D_%=;\n\t"
            "bra.uni W_%=;\n\t"
            "D_%=:\n\t"
            "}"
            :: "r"(addr), "r"(parity) : "memory");
    }
}

__device__ __forceinline__ void tma_copy(uint32_t mb, uint32_t dst,
                                         const char* src, uint32_t bytes)
{
    asm volatile(
        "cp.async.bulk.shared::cluster.global.mbarrier::complete_tx::bytes "
        "[%0], [%1], %2, [%3];"
        :: "r"(dst), "l"(src), "r"(bytes), "r"(mb) : "memory");
}

__global__ __launch_bounds__(THREADS)
void attn_loc_kernel(const int* __restrict__ his,
                     const int* __restrict__ cur,
                     const float* __restrict__ mat,
                     float* __restrict__ out)
{
    __shared__ alignas(128) float srow[N_POI];        // 40000 B: row0, then row1 tail
    __shared__ alignas(128) float headbuf[HEAD_ELEMS];// 16000 B: row1 head [0,4000)
    __shared__ float sred[THREADS / 32];
    __shared__ alignas(8) uint64_t mbar[2];

    const int tid  = threadIdx.x;
    const int row0 = blockIdx.x;
    const int row1 = blockIdx.x + GRID;
    const uint32_t mb0 = (uint32_t)__cvta_generic_to_shared(&mbar[0]);
    const uint32_t mb1 = (uint32_t)__cvta_generic_to_shared(&mbar[1]);
    const uint32_t dst = (uint32_t)__cvta_generic_to_shared(srow);
    const uint32_t dsh = (uint32_t)__cvta_generic_to_shared(headbuf);

    const char* src1 = nullptr;
    if (tid == 0) {
        asm volatile("mbarrier.init.shared.b64 [%0], %1;" :: "r"(mb0), "r"(1) : "memory");
        asm volatile("mbarrier.init.shared.b64 [%0], %1;" :: "r"(mb1), "r"(1) : "memory");
        const char* src0 = (const char*)mat + (size_t)__ldg(cur + row0) * ROW_BYTES;
        src1             = (const char*)mat + (size_t)__ldg(cur + row1) * ROW_BYTES;

        // row0: full row in flight immediately
        asm volatile("mbarrier.arrive.expect_tx.shared.b64 _, [%0], %1;"
                     :: "r"(mb0), "r"((uint32_t)ROW_BYTES) : "memory");
        tma_copy(mb0, dst, src0, ROW_BYTES);

        // row1: post the FULL 40KB expectation now, ship the 16KB head now
        // (streams concurrently with row0); the 24KB tail ships after gather0.
        // mb1 flips only when all 40000 bytes have landed.
        asm volatile("mbarrier.arrive.expect_tx.shared.b64 _, [%0], %1;"
                     :: "r"(mb1), "r"((uint32_t)ROW_BYTES) : "memory");
        tma_copy(mb1, dsh, src1, HEAD_BYTES);
    }

    // Index prefetch overlaps the TMA flights (his is tiny, L2-resident).
    int cidx[PER_T];
#pragma unroll
    for (int k = 0; k < PER_T; k++)
        cidx[k] = __ldg(his + tid + k * THREADS);

    __syncthreads();                     // publish mbarrier inits

#pragma unroll
    for (int half = 0; half < 2; half++) {
        mbar_wait(half ? mb1 : mb0, 0u); // this row fully landed

        // Gather: row0 entirely from srow; row1 head from headbuf, tail from
        // srow (natural positions). half is compile-time -> row0 path has no
        // select overhead.
        float v[PER_T];
        float mx = -INFINITY;
#pragma unroll
        for (int k = 0; k < PER_T; k++) {
            const int c = cidx[k];
            const float d = (half == 1 && c < HEAD_ELEMS) ? headbuf[c] : srow[c];
            const float e = (d != 0.0f) ? __fdividef(1.0f, d) : EPS_VAL;
            v[k] = e;
            mx = fmaxf(mx, e);
        }

        // Block max reduction
#pragma unroll
        for (int o = 16; o; o >>= 1)
            mx = fmaxf(mx, __shfl_xor_sync(0xffffffffu, mx, o));
        if ((tid & 31) == 0) sred[tid >> 5] = mx;
        __syncthreads();                 // all srow reads for row0 complete

        // Ship row1's 24KB tail into srow[4000..] — overlaps row0's epilogue.
        if (half == 0 && tid == 0)
            tma_copy(mb1, dst + HEAD_BYTES, src1 + HEAD_BYTES, TAIL_BYTES);

        float bmax = sred[0];
#pragma unroll
        for (int w = 1; w < THREADS / 32; w++) bmax = fmaxf(bmax, sred[w]);
        __syncthreads();

        // exp + local sum
        float sum = 0.0f;
#pragma unroll
        for (int k = 0; k < PER_T; k++) {
            const float e = __expf(v[k] - bmax);
            v[k] = e;
            sum += e;
        }

        // Block sum reduction
#pragma unroll
        for (int o = 16; o; o >>= 1)
            sum += __shfl_xor_sync(0xffffffffu, sum, o);
        if ((tid & 31) == 0) sred[tid >> 5] = sum;
        __syncthreads();
        float bsum = 0.0f;
#pragma unroll
        for (int w = 0; w < THREADS / 32; w++) bsum += sred[w];
        __syncthreads();                 // sred safe to reuse next half

        // Normalize + coalesced store
        const float inv = __fdividef(1.0f, bsum);
        const int row = half ? row1 : row0;
        float* __restrict__ orow = out + (size_t)row * SEQ_LEN;
#pragma unroll
        for (int k = 0; k < PER_T; k++)
            orow[tid + k * THREADS] = v[k] * inv;
    }
}

extern "C" void kernel_launch(void* const* d_in, const int* in_sizes, int n_in,
                              void* d_out, int out_size)
{
    const int*   his = (const int*)d_in[0];
    const int*   cur = (const int*)d_in[1];
    const float* mat = (const float*)d_in[2];
    float*       out = (float*)d_out;

    attn_loc_kernel<<<GRID, THREADS>>>(his, cur, mat, out);
}

// round 15
// speedup vs baseline: 1.4760x; 1.4760x over previous
#include <cuda_runtime.h>
#include <cstdint>

#define SEQ_LEN   2048
#define STATE_LEN 1024
#define N_POI     10000
#define ROW_BYTES (N_POI * 4)            // 40000, 16B-aligned
#define EPS_VAL   1e-6f
#define THREADS   256
#define PER_T     (SEQ_LEN / THREADS)    // 8
#define GRID      (STATE_LEN / 2)        // 512 CTAs -> single wave, 2 rows each

__device__ __forceinline__ void mbar_wait(uint32_t addr, uint32_t parity)
{
    uint32_t done;
    asm volatile(
        "{\n\t"
        ".reg .pred p;\n\t"
        "mbarrier.try_wait.parity.acquire.cta.shared::cta.b64 p, [%1], %2;\n\t"
        "selp.b32 %0, 1, 0, p;\n\t"
        "}"
        : "=r"(done) : "r"(addr), "r"(parity) : "memory");
    if (!done) {
        asm volatile(
            "{\n\t"
            ".reg .pred P1;\n\t"
            "W_%=:\n\t"
            "mbarrier.try_wait.parity.acquire.cta.shared::cta.b64 P1, [%0], %1, 0x989680;\n\t"
            "@P1 bra.uni D_%=;\n\t"
            "bra.uni W_%=;\n\t"
            "D_%=:\n\t"
            "}"
            :: "r"(addr), "r"(parity) : "memory");
    }
}

__device__ __forceinline__ void tma_row(uint32_t mb, uint32_t dst, const char* src)
{
    asm volatile("mbarrier.arrive.expect_tx.shared.b64 _, [%0], %1;"
                 :: "r"(mb), "r"((uint32_t)ROW_BYTES) : "memory");
    asm volatile(
        "cp.async.bulk.shared::cluster.global.mbarrier::complete_tx::bytes "
        "[%0], [%1], %2, [%3];"
        :: "r"(dst), "l"(src), "r"((uint32_t)ROW_BYTES), "r"(mb) : "memory");
}

__global__ __launch_bounds__(THREADS)
void attn_loc_kernel(const int* __restrict__ his,
                     const int* __restrict__ cur,
                     const float* __restrict__ mat,
                     float* __restrict__ out)
{
    __shared__ alignas(128) float srow[N_POI];   // 40000 B single buffer
    __shared__ float sred[THREADS / 32];
    __shared__ alignas(8) uint64_t mbar;

    const int tid  = threadIdx.x;
    const int row0 = blockIdx.x;
    const int row1 = blockIdx.x + GRID;
    const uint32_t mb  = (uint32_t)__cvta_generic_to_shared(&mbar);
    const uint32_t dst = (uint32_t)__cvta_generic_to_shared(srow);

    const char* src1 = nullptr;
    if (tid == 0) {
        asm volatile("mbarrier.init.shared.b64 [%0], %1;"
                     :: "r"(mb), "r"(1) : "memory");
        const char* src0 = (const char*)mat + (size_t)__ldg(cur + row0) * ROW_BYTES;
        src1             = (const char*)mat + (size_t)__ldg(cur + row1) * ROW_BYTES;
        tma_row(mb, dst, src0);          // row0 in flight immediately
    }

    // Index prefetch overlaps the TMA flight (his is tiny, L2-resident).
    int cidx[PER_T];
#pragma unroll
    for (int k = 0; k < PER_T; k++)
        cidx[k] = __ldg(his + tid + k * THREADS);

    __syncthreads();                     // publish mbarrier init

#pragma unroll
    for (int half = 0; half < 2; half++) {
        mbar_wait(mb, (uint32_t)half);   // row landed (parity 0 then 1)

        // Gather from smem into registers, local max
        float v[PER_T];
        float mx = -INFINITY;
#pragma unroll
        for (int k = 0; k < PER_T; k++) {
            const float d = srow[cidx[k]];
            const float e = (d != 0.0f) ? __fdividef(1.0f, d) : EPS_VAL;
            v[k] = e;
            mx = fmaxf(mx, e);
        }

        // Block max reduction
#pragma unroll
        for (int o = 16; o; o >>= 1)
            mx = fmaxf(mx, __shfl_xor_sync(0xffffffffu, mx, o));
        if ((tid & 31) == 0) sred[tid >> 5] = mx;
        __syncthreads();                 // all srow reads complete here

        // Prefetch row1 into the SAME buffer: its flight overlaps row0's
        // entire epilogue (reductions + exp + store).
        if (half == 0 && tid == 0)
            tma_row(mb, dst, src1);

        float bmax = sred[0];
#pragma unroll
        for (int w = 1; w < THREADS / 32; w++) bmax = fmaxf(bmax, sred[w]);
        __syncthreads();

        // exp + local sum
        float sum = 0.0f;
#pragma unroll
        for (int k = 0; k < PER_T; k++) {
            const float e = __expf(v[k] - bmax);
            v[k] = e;
            sum += e;
        }

        // Block sum reduction
#pragma unroll
        for (int o = 16; o; o >>= 1)
            sum += __shfl_xor_sync(0xffffffffu, sum, o);
        if ((tid & 31) == 0) sred[tid >> 5] = sum;
        __syncthreads();
        float bsum = 0.0f;
#pragma unroll
        for (int w = 0; w < THREADS / 32; w++) bsum += sred[w];
        __syncthreads();                 // sred safe to reuse next half

        // Normalize + coalesced store
        const float inv = __fdividef(1.0f, bsum);
        const int row = half ? row1 : row0;
        float* __restrict__ orow = out + (size_t)row * SEQ_LEN;
#pragma unroll
        for (int k = 0; k < PER_T; k++)
            orow[tid + k * THREADS] = v[k] * inv;
    }
}

extern "C" void kernel_launch(void* const* d_in, const int* in_sizes, int n_in,
                              void* d_out, int out_size)
{
    const int*   his = (const int*)d_in[0];
    const int*   cur = (const int*)d_in[1];
    const float* mat = (const float*)d_in[2];
    float*       out = (float*)d_out;

    attn_loc_kernel<<<GRID, THREADS>>>(his, cur, mat, out);
}